// round 2
// baseline (speedup 1.0000x reference)
#include <cuda_runtime.h>
#include <cstdint>

// Problem dims (fixed for this problem instance)
#define LTOK 16384
#define LCHK 8192
#define HID  4096
#define GRP  64
#define CSZ  (LCHK / GRP)   // 128 chunks per group
#define TW   512            // hidden columns per CTA (128 threads x float4)
#define H4   (HID / 4)      // 1024 float4 lanes

// -------- device scratch (no allocations allowed) --------
__device__ int   g_idx[LCHK + 1];          // boundary token index per chunk (+ sentinel = LTOK)
__device__ float g_a[LCHK];                // decay coefficient per chunk (a[0]=0)
__device__ float g_bs[LCHK];               // b scale per chunk (p, except chunk0 -> 1)
__device__ float g_P[LCHK];                // within-group inclusive prefix product of a
__device__ float g_A[GRP];                 // per-group total product of a
__device__ float g_L[GRP * HID];           // per-group local scan end value
__device__ float g_In[GRP * HID];          // per-group incoming carry (y at end of prev group)

// ---------------------------------------------------------
// Kernel 1: detect mask dtype, scan boundary mask, build per-chunk scalars
// + per-group products. Single CTA of 1024 threads.
// ---------------------------------------------------------
__global__ void __launch_bounds__(1024) setup_kernel(const void* __restrict__ mask_raw,
                                                     const float* __restrict__ probs) {
    __shared__ int part[1024];
    __shared__ int s_nonbin, s_offmod;
    const int t = threadIdx.x;

    // ---- dtype sniff on first 16KB (safe for u8/i32/f32 storage) ----
    if (t == 0) { s_nonbin = 0; s_offmod = 0; }
    __syncthreads();
    {
        const unsigned char* u8 = (const unsigned char*)mask_raw;
        int nonbin = 0, offmod = 0;
        for (int i = t; i < LTOK; i += 1024) {
            unsigned char v = u8[i];
            if (v > 1) nonbin = 1;
            if (v != 0 && (i & 3) != 0) offmod = 1;
        }
        if (nonbin) atomicOr(&s_nonbin, 1);
        if (offmod) atomicOr(&s_offmod, 1);
    }
    __syncthreads();
    const int mode = s_nonbin ? 2 : (s_offmod ? 0 : 1);  // 0=u8, 1=i32, 2=f32

    const unsigned char* mu8 = (const unsigned char*)mask_raw;
    const int*           mi  = (const int*)mask_raw;
    const float*         mf  = (const float*)mask_raw;

    const int PER = LTOK / 1024;  // 16 tokens per thread
    const int base = t * PER;

    unsigned char m[PER];
    int cnt = 0;
#pragma unroll
    for (int i = 0; i < PER; i++) {
        const int tok = base + i;
        unsigned char v;
        if (mode == 0)      v = (mu8[tok] != 0);
        else if (mode == 1) v = (mi[tok] != 0);
        else                v = (mf[tok] != 0.0f);
        m[i] = v;
        cnt += v;
    }
    part[t] = cnt;
    __syncthreads();

    // Hillis-Steele inclusive scan over the 1024 partial counts
    for (int off = 1; off < 1024; off <<= 1) {
        int v = (t >= off) ? part[t - off] : 0;
        __syncthreads();
        part[t] += v;
        __syncthreads();
    }

    int run = part[t] - cnt;  // exclusive prefix
#pragma unroll
    for (int i = 0; i < PER; i++) {
        if (m[i]) { g_idx[run] = base + i; run++; }
    }
    __syncthreads();
    if (t == 0) g_idx[part[1023]] = LTOK;  // sentinel after last chunk
    __syncthreads();

    // per-chunk scalars
    for (int c = t; c < LCHK; c += 1024) {
        float p = probs[g_idx[c]];
        g_a[c]  = (c == 0) ? 0.0f : (1.0f - p);
        g_bs[c] = (c == 0) ? 1.0f : p;
    }
    __syncthreads();

    // per-group scalar prefix products
    if (t < GRP) {
        float prod = 1.0f;
        const int b0 = t * CSZ;
        for (int k = 0; k < CSZ; k++) {
            prod *= g_a[b0 + k];
            g_P[b0 + k] = prod;
        }
        g_A[t] = prod;
    }
}

// ---------------------------------------------------------
// Kernel 2: per-(group, hidden tile) local scan -> group end value L.
// grid (HID/TW, GRP), block 128, each thread owns a float4 lane.
// ---------------------------------------------------------
__global__ void __launch_bounds__(128) passA_kernel(const float* __restrict__ conc) {
    const int g  = blockIdx.y;
    const int c0 = g * CSZ;
    __shared__ float sa[CSZ], sb[CSZ];
    for (int i = threadIdx.x; i < CSZ; i += 128) {
        sa[i] = g_a[c0 + i];
        sb[i] = g_bs[c0 + i];
    }
    __syncthreads();

    const int col4 = blockIdx.x * 128 + threadIdx.x;
    const float4* cp = reinterpret_cast<const float4*>(conc) + (size_t)c0 * H4 + col4;

    float4 y = make_float4(0.f, 0.f, 0.f, 0.f);
#pragma unroll 1
    for (int cc = 0; cc < CSZ; cc += 8) {
        float4 v[8];
#pragma unroll
        for (int j = 0; j < 8; j++) v[j] = cp[(size_t)(cc + j) * H4];
#pragma unroll
        for (int j = 0; j < 8; j++) {
            const float a = sa[cc + j], b = sb[cc + j];
            y.x = fmaf(y.x, a, v[j].x * b);
            y.y = fmaf(y.y, a, v[j].y * b);
            y.z = fmaf(y.z, a, v[j].z * b);
            y.w = fmaf(y.w, a, v[j].w * b);
        }
    }
    reinterpret_cast<float4*>(g_L)[(size_t)g * H4 + col4] = y;
}

// ---------------------------------------------------------
// Kernel 3: carry scan across groups per hidden lane.
// grid (H4/256), block 256.
// ---------------------------------------------------------
__global__ void __launch_bounds__(256) passB_kernel() {
    __shared__ float sA[GRP];
    if (threadIdx.x < GRP) sA[threadIdx.x] = g_A[threadIdx.x];
    __syncthreads();

    const int col4 = blockIdx.x * 256 + threadIdx.x;  // 0..1023
    const float4* Lp = reinterpret_cast<const float4*>(g_L);
    float4* Ip = reinterpret_cast<float4*>(g_In);

    float4 E = make_float4(0.f, 0.f, 0.f, 0.f);
#pragma unroll 1
    for (int gg = 0; gg < GRP; gg += 8) {
        float4 lv[8];
#pragma unroll
        for (int j = 0; j < 8; j++) lv[j] = Lp[(size_t)(gg + j) * H4 + col4];
#pragma unroll
        for (int j = 0; j < 8; j++) {
            Ip[(size_t)(gg + j) * H4 + col4] = E;  // incoming carry for group gg+j
            const float A = sA[gg + j];
            E.x = fmaf(A, E.x, lv[j].x);
            E.y = fmaf(A, E.y, lv[j].y);
            E.z = fmaf(A, E.z, lv[j].z);
            E.w = fmaf(A, E.w, lv[j].w);
        }
    }
}

// ---------------------------------------------------------
// Kernel 4: recompute local scan, add carry*P, scatter to all tokens of each chunk.
// grid (HID/TW, GRP), block 128.
// ---------------------------------------------------------
__global__ void __launch_bounds__(128) passC_kernel(const float* __restrict__ conc,
                                                    float* __restrict__ out) {
    const int g  = blockIdx.y;
    const int c0 = g * CSZ;
    __shared__ float sa[CSZ], sb[CSZ], sP[CSZ];
    __shared__ int sidx[CSZ + 1];
    for (int i = threadIdx.x; i < CSZ; i += 128) {
        sa[i]  = g_a[c0 + i];
        sb[i]  = g_bs[c0 + i];
        sP[i]  = g_P[c0 + i];
        sidx[i] = g_idx[c0 + i];
    }
    if (threadIdx.x == 0) sidx[CSZ] = g_idx[c0 + CSZ];
    __syncthreads();

    const int col4 = blockIdx.x * 128 + threadIdx.x;
    const float4* cp = reinterpret_cast<const float4*>(conc) + (size_t)c0 * H4 + col4;
    float4* op = reinterpret_cast<float4*>(out);

    const float4 carry = reinterpret_cast<const float4*>(g_In)[(size_t)g * H4 + col4];
    float4 y = make_float4(0.f, 0.f, 0.f, 0.f);

#pragma unroll 1
    for (int cc = 0; cc < CSZ; cc += 8) {
        float4 v[8];
#pragma unroll
        for (int j = 0; j < 8; j++) v[j] = cp[(size_t)(cc + j) * H4];
#pragma unroll
        for (int j = 0; j < 8; j++) {
            const float a = sa[cc + j], b = sb[cc + j], Pv = sP[cc + j];
            y.x = fmaf(y.x, a, v[j].x * b);
            y.y = fmaf(y.y, a, v[j].y * b);
            y.z = fmaf(y.z, a, v[j].z * b);
            y.w = fmaf(y.w, a, v[j].w * b);
            float4 yt;
            yt.x = fmaf(carry.x, Pv, y.x);
            yt.y = fmaf(carry.y, Pv, y.y);
            yt.z = fmaf(carry.z, Pv, y.z);
            yt.w = fmaf(carry.w, Pv, y.w);
            const int t0 = sidx[cc + j];
            const int t1 = sidx[cc + j + 1];
            for (int tok = t0; tok < t1; ++tok) {
                op[(size_t)tok * H4 + col4] = yt;
            }
        }
    }
}

// ---------------------------------------------------------
extern "C" void kernel_launch(void* const* d_in, const int* in_sizes, int n_in,
                              void* d_out, int out_size) {
    const float* conc = (const float*)d_in[0];   // [1, LCHK, HID] f32
    const float* probs = (const float*)d_in[1];  // [1, LTOK, 1]   f32
    const void*  mask = d_in[2];                 // [1, LTOK] bool (dtype sniffed on device)
    float* out = (float*)d_out;                  // [1, LTOK, HID] f32

    setup_kernel<<<1, 1024>>>(mask, probs);
    passA_kernel<<<dim3(HID / TW, GRP), 128>>>(conc);
    passB_kernel<<<dim3(H4 / 256), 256>>>();
    passC_kernel<<<dim3(HID / TW, GRP), 128>>>(conc, out);
}

// round 3
// speedup vs baseline: 1.0517x; 1.0517x over previous
#include <cuda_runtime.h>
#include <cstdint>

// Problem dims (fixed for this problem instance)
#define LTOK 16384
#define LCHK 8192
#define HID  4096
#define GRP  256
#define CSZ  (LCHK / GRP)   // 32 chunks per group
#define TW   512            // hidden columns per CTA (128 threads x float4)
#define H4   (HID / 4)      // 1024 float4 lanes

// -------- device scratch (no allocations allowed) --------
__device__ int   g_idx[LCHK + 1];          // boundary token index per chunk (+ sentinel = LTOK)
__device__ float g_a[LCHK];                // decay coefficient per chunk (a[0]=0)
__device__ float g_bs[LCHK];               // b scale per chunk (p, except chunk0 -> 1)
__device__ float g_P[LCHK];                // within-group inclusive prefix product of a
__device__ float g_A[GRP];                 // per-group total product of a
__device__ float g_L[GRP * HID];           // per-group local scan end value
__device__ float g_In[GRP * HID];          // per-group incoming carry (y at end of prev group)

// ---------------------------------------------------------
// Kernel 1: detect mask dtype, scan boundary mask, build per-chunk scalars
// + per-group products. Single CTA of 1024 threads.
// ---------------------------------------------------------
__global__ void __launch_bounds__(1024) setup_kernel(const void* __restrict__ mask_raw,
                                                     const float* __restrict__ probs) {
    __shared__ int part[1024];
    __shared__ int s_nonbin, s_offmod;
    const int t = threadIdx.x;

    // ---- dtype sniff (safe for u8/i32/f32 storage) ----
    if (t == 0) { s_nonbin = 0; s_offmod = 0; }
    __syncthreads();
    {
        const unsigned char* u8 = (const unsigned char*)mask_raw;
        int nonbin = 0, offmod = 0;
        for (int i = t; i < LTOK; i += 1024) {
            unsigned char v = u8[i];
            if (v > 1) nonbin = 1;
            if (v != 0 && (i & 3) != 0) offmod = 1;
        }
        if (nonbin) atomicOr(&s_nonbin, 1);
        if (offmod) atomicOr(&s_offmod, 1);
    }
    __syncthreads();
    const int mode = s_nonbin ? 2 : (s_offmod ? 0 : 1);  // 0=u8, 1=i32, 2=f32

    const unsigned char* mu8 = (const unsigned char*)mask_raw;
    const int*           mi  = (const int*)mask_raw;
    const float*         mf  = (const float*)mask_raw;

    const int PER = LTOK / 1024;  // 16 tokens per thread
    const int base = t * PER;

    unsigned char m[PER];
    int cnt = 0;
#pragma unroll
    for (int i = 0; i < PER; i++) {
        const int tok = base + i;
        unsigned char v;
        if (mode == 0)      v = (mu8[tok] != 0);
        else if (mode == 1) v = (mi[tok] != 0);
        else                v = (mf[tok] != 0.0f);
        m[i] = v;
        cnt += v;
    }
    part[t] = cnt;
    __syncthreads();

    // Hillis-Steele inclusive scan over the 1024 partial counts
    for (int off = 1; off < 1024; off <<= 1) {
        int v = (t >= off) ? part[t - off] : 0;
        __syncthreads();
        part[t] += v;
        __syncthreads();
    }

    int run = part[t] - cnt;  // exclusive prefix
#pragma unroll
    for (int i = 0; i < PER; i++) {
        if (m[i]) { g_idx[run] = base + i; run++; }
    }
    __syncthreads();
    if (t == 0) g_idx[part[1023]] = LTOK;  // sentinel after last chunk
    __syncthreads();

    // per-chunk scalars
    for (int c = t; c < LCHK; c += 1024) {
        float p = probs[g_idx[c]];
        g_a[c]  = (c == 0) ? 0.0f : (1.0f - p);
        g_bs[c] = (c == 0) ? 1.0f : p;
    }
    __syncthreads();

    // per-group scalar prefix products
    if (t < GRP) {
        float prod = 1.0f;
        const int b0 = t * CSZ;
        for (int k = 0; k < CSZ; k++) {
            prod *= g_a[b0 + k];
            g_P[b0 + k] = prod;
        }
        g_A[t] = prod;
    }
}

// ---------------------------------------------------------
// Kernel 2: per-(group, hidden tile) local scan -> group end value L.
// grid (HID/TW, GRP) = (8, 256) = 2048 CTAs, block 128.
// ---------------------------------------------------------
__global__ void __launch_bounds__(128) passA_kernel(const float* __restrict__ conc) {
    const int g  = blockIdx.y;
    const int c0 = g * CSZ;
    __shared__ float sa[CSZ], sb[CSZ];
    if (threadIdx.x < CSZ) {
        sa[threadIdx.x] = g_a[c0 + threadIdx.x];
        sb[threadIdx.x] = g_bs[c0 + threadIdx.x];
    }
    __syncthreads();

    const int col4 = blockIdx.x * 128 + threadIdx.x;
    const float4* cp = reinterpret_cast<const float4*>(conc) + (size_t)c0 * H4 + col4;

    float4 y = make_float4(0.f, 0.f, 0.f, 0.f);
#pragma unroll 1
    for (int cc = 0; cc < CSZ; cc += 8) {
        float4 v[8];
#pragma unroll
        for (int j = 0; j < 8; j++) v[j] = __ldcs(&cp[(size_t)(cc + j) * H4]);
#pragma unroll
        for (int j = 0; j < 8; j++) {
            const float a = sa[cc + j], b = sb[cc + j];
            y.x = fmaf(y.x, a, v[j].x * b);
            y.y = fmaf(y.y, a, v[j].y * b);
            y.z = fmaf(y.z, a, v[j].z * b);
            y.w = fmaf(y.w, a, v[j].w * b);
        }
    }
    reinterpret_cast<float4*>(g_L)[(size_t)g * H4 + col4] = y;
}

// ---------------------------------------------------------
// Kernel 3: carry scan across groups per hidden lane.
// grid (H4/256) = 4, block 256.
// ---------------------------------------------------------
__global__ void __launch_bounds__(256) passB_kernel() {
    __shared__ float sA[GRP];
    if (threadIdx.x < GRP) sA[threadIdx.x] = g_A[threadIdx.x];
    __syncthreads();

    const int col4 = blockIdx.x * 256 + threadIdx.x;  // 0..1023
    const float4* Lp = reinterpret_cast<const float4*>(g_L);
    float4* Ip = reinterpret_cast<float4*>(g_In);

    float4 E = make_float4(0.f, 0.f, 0.f, 0.f);
#pragma unroll 1
    for (int gg = 0; gg < GRP; gg += 8) {
        float4 lv[8];
#pragma unroll
        for (int j = 0; j < 8; j++) lv[j] = Lp[(size_t)(gg + j) * H4 + col4];
#pragma unroll
        for (int j = 0; j < 8; j++) {
            Ip[(size_t)(gg + j) * H4 + col4] = E;  // incoming carry for group gg+j
            const float A = sA[gg + j];
            E.x = fmaf(A, E.x, lv[j].x);
            E.y = fmaf(A, E.y, lv[j].y);
            E.z = fmaf(A, E.z, lv[j].z);
            E.w = fmaf(A, E.w, lv[j].w);
        }
    }
}

// ---------------------------------------------------------
// Kernel 4: recompute local scan, add carry*P, scatter to all tokens of each chunk.
// grid (HID/TW, GRP) = (8, 256) = 2048 CTAs, block 128.
// ---------------------------------------------------------
__global__ void __launch_bounds__(128) passC_kernel(const float* __restrict__ conc,
                                                    float* __restrict__ out) {
    const int g  = blockIdx.y;
    const int c0 = g * CSZ;
    __shared__ float sa[CSZ], sb[CSZ], sP[CSZ];
    __shared__ int sidx[CSZ + 1];
    if (threadIdx.x < CSZ) {
        sa[threadIdx.x]  = g_a[c0 + threadIdx.x];
        sb[threadIdx.x]  = g_bs[c0 + threadIdx.x];
        sP[threadIdx.x]  = g_P[c0 + threadIdx.x];
        sidx[threadIdx.x] = g_idx[c0 + threadIdx.x];
    }
    if (threadIdx.x == 0) sidx[CSZ] = g_idx[c0 + CSZ];
    __syncthreads();

    const int col4 = blockIdx.x * 128 + threadIdx.x;
    const float4* cp = reinterpret_cast<const float4*>(conc) + (size_t)c0 * H4 + col4;
    float4* op = reinterpret_cast<float4*>(out);

    const float4 carry = reinterpret_cast<const float4*>(g_In)[(size_t)g * H4 + col4];
    float4 y = make_float4(0.f, 0.f, 0.f, 0.f);

#pragma unroll 1
    for (int cc = 0; cc < CSZ; cc += 8) {
        float4 v[8];
#pragma unroll
        for (int j = 0; j < 8; j++) v[j] = __ldcs(&cp[(size_t)(cc + j) * H4]);
#pragma unroll
        for (int j = 0; j < 8; j++) {
            const float a = sa[cc + j], b = sb[cc + j], Pv = sP[cc + j];
            y.x = fmaf(y.x, a, v[j].x * b);
            y.y = fmaf(y.y, a, v[j].y * b);
            y.z = fmaf(y.z, a, v[j].z * b);
            y.w = fmaf(y.w, a, v[j].w * b);
            float4 yt;
            yt.x = fmaf(carry.x, Pv, y.x);
            yt.y = fmaf(carry.y, Pv, y.y);
            yt.z = fmaf(carry.z, Pv, y.z);
            yt.w = fmaf(carry.w, Pv, y.w);
            const int t0 = sidx[cc + j];
            const int t1 = sidx[cc + j + 1];
            for (int tok = t0; tok < t1; ++tok) {
                __stcs(&op[(size_t)tok * H4 + col4], yt);
            }
        }
    }
}

// ---------------------------------------------------------
extern "C" void kernel_launch(void* const* d_in, const int* in_sizes, int n_in,
                              void* d_out, int out_size) {
    const float* conc = (const float*)d_in[0];   // [1, LCHK, HID] f32
    const float* probs = (const float*)d_in[1];  // [1, LTOK, 1]   f32
    const void*  mask = d_in[2];                 // [1, LTOK] bool (dtype sniffed on device)
    float* out = (float*)d_out;                  // [1, LTOK, HID] f32

    setup_kernel<<<1, 1024>>>(mask, probs);
    passA_kernel<<<dim3(HID / TW, GRP), 128>>>(conc);
    passB_kernel<<<dim3(H4 / 256), 256>>>();
    passC_kernel<<<dim3(HID / TW, GRP), 128>>>(conc, out);
}